// round 1
// baseline (speedup 1.0000x reference)
#include <cuda_runtime.h>
#include <cstdint>

#define N_LEVELS 16
#define LOG2_T 19
#define HASH_MASK ((1u << LOG2_T) - 1u)
#define P0 73856093u
#define P1 19349663u
#define P2 83492791u

// floor(16 * 2^(l/3)) through the reference's fp32 chain (verified rounding
// direction: b = 2^(1/3)*(1+1.86e-8), so powers of two round UP -> exact ints).
__constant__ float c_res[N_LEVELS] = {
    16.f, 20.f, 25.f, 32.f, 40.f, 50.f, 64.f, 80.f,
    101.f, 128.f, 161.f, 203.f, 256.f, 322.f, 406.f, 512.f
};

__global__ void __launch_bounds__(256) hashenc_kernel(
    const float* __restrict__ x,
    const float* __restrict__ emb,
    float* __restrict__ out,
    int B)
{
    const int i = blockIdx.x * blockDim.x + threadIdx.x;
    if (i >= B) return;

    float px = x[3 * i + 0];
    float py = x[3 * i + 1];
    float pz = x[3 * i + 2];
    // clip to box
    px = fminf(fmaxf(px, -1.0f), 1.0f);
    py = fminf(fmaxf(py, -1.0f), 1.0f);
    pz = fminf(fmaxf(pz, -1.0f), 1.0f);

    float o[2 * N_LEVELS];

    #pragma unroll
    for (int l = 0; l < N_LEVELS; l++) {
        const float res = c_res[l];
        const float gs = __fdiv_rn(2.0f, res);   // (BOX_MAX-BOX_MIN)/res

        // ---- x dim (mirror reference fp32 op order exactly) ----
        float tx  = __fdiv_rn(__fsub_rn(px, -1.0f), gs);
        float fbx = floorf(tx);
        int   bx  = (int)fbx;
        float vx  = __fadd_rn(__fmul_rn(fbx, gs), -1.0f);
        float wx  = __fdiv_rn(__fsub_rn(px, vx), gs);
        // ---- y dim ----
        float ty  = __fdiv_rn(__fsub_rn(py, -1.0f), gs);
        float fby = floorf(ty);
        int   by  = (int)fby;
        float vy  = __fadd_rn(__fmul_rn(fby, gs), -1.0f);
        float wy  = __fdiv_rn(__fsub_rn(py, vy), gs);
        // ---- z dim ----
        float tz  = __fdiv_rn(__fsub_rn(pz, -1.0f), gs);
        float fbz = floorf(tz);
        int   bz  = (int)fbz;
        float vz  = __fadd_rn(__fmul_rn(fbz, gs), -1.0f);
        float wz  = __fdiv_rn(__fsub_rn(pz, vz), gs);

        // ---- hashes for the 8 corners (int32 wraparound, XOR, mask) ----
        unsigned hx0 = (unsigned)bx * P0, hx1 = hx0 + P0;
        unsigned hy0 = (unsigned)by * P1, hy1 = hy0 + P1;
        unsigned hz0 = (unsigned)bz * P2, hz1 = hz0 + P2;

        // corner index c = 4*i + 2*j + k (i=x, j=y, k=z)
        unsigned h0 = (hx0 ^ hy0 ^ hz0) & HASH_MASK;
        unsigned h1 = (hx0 ^ hy0 ^ hz1) & HASH_MASK;
        unsigned h2 = (hx0 ^ hy1 ^ hz0) & HASH_MASK;
        unsigned h3 = (hx0 ^ hy1 ^ hz1) & HASH_MASK;
        unsigned h4 = (hx1 ^ hy0 ^ hz0) & HASH_MASK;
        unsigned h5 = (hx1 ^ hy0 ^ hz1) & HASH_MASK;
        unsigned h6 = (hx1 ^ hy1 ^ hz0) & HASH_MASK;
        unsigned h7 = (hx1 ^ hy1 ^ hz1) & HASH_MASK;

        const float2* tbl = (const float2*)emb + ((size_t)l << LOG2_T);

        // issue all 8 gathers before consuming (MLP)
        float2 e0 = __ldg(tbl + h0);
        float2 e1 = __ldg(tbl + h1);
        float2 e2 = __ldg(tbl + h2);
        float2 e3 = __ldg(tbl + h3);
        float2 e4 = __ldg(tbl + h4);
        float2 e5 = __ldg(tbl + h5);
        float2 e6 = __ldg(tbl + h6);
        float2 e7 = __ldg(tbl + h7);

        // trilinear weights, product order ((sx*sy)*sz)
        float wx0 = __fsub_rn(1.0f, wx);
        float wy0 = __fsub_rn(1.0f, wy);
        float wz0 = __fsub_rn(1.0f, wz);

        float cxy00 = wx0 * wy0;
        float cxy01 = wx0 * wy;
        float cxy10 = wx  * wy0;
        float cxy11 = wx  * wy;

        float c0 = cxy00 * wz0;
        float c1 = cxy00 * wz;
        float c2 = cxy01 * wz0;
        float c3 = cxy01 * wz;
        float c4 = cxy10 * wz0;
        float c5 = cxy10 * wz;
        float c6 = cxy11 * wz0;
        float c7 = cxy11 * wz;

        float a0, a1;
        a0 = c0 * e0.x;            a1 = c0 * e0.y;
        a0 = fmaf(c1, e1.x, a0);   a1 = fmaf(c1, e1.y, a1);
        a0 = fmaf(c2, e2.x, a0);   a1 = fmaf(c2, e2.y, a1);
        a0 = fmaf(c3, e3.x, a0);   a1 = fmaf(c3, e3.y, a1);
        a0 = fmaf(c4, e4.x, a0);   a1 = fmaf(c4, e4.y, a1);
        a0 = fmaf(c5, e5.x, a0);   a1 = fmaf(c5, e5.y, a1);
        a0 = fmaf(c6, e6.x, a0);   a1 = fmaf(c6, e6.y, a1);
        a0 = fmaf(c7, e7.x, a0);   a1 = fmaf(c7, e7.y, a1);

        o[2 * l + 0] = a0;
        o[2 * l + 1] = a1;
    }

    // each thread owns a fully-aligned 128B output row -> 8x STG.128
    float4* po = (float4*)(out + (size_t)i * (2 * N_LEVELS));
    #pragma unroll
    for (int s = 0; s < 8; s++) {
        po[s] = make_float4(o[4 * s + 0], o[4 * s + 1], o[4 * s + 2], o[4 * s + 3]);
    }
}

extern "C" void kernel_launch(void* const* d_in, const int* in_sizes, int n_in,
                              void* d_out, int out_size) {
    const float* x   = (const float*)d_in[0];
    const float* emb = (const float*)d_in[1];
    float* out = (float*)d_out;
    const int B = in_sizes[0] / 3;

    const int threads = 256;
    const int blocks = (B + threads - 1) / threads;
    hashenc_kernel<<<blocks, threads>>>(x, emb, out, B);
}

// round 2
// speedup vs baseline: 1.1927x; 1.1927x over previous
#include <cuda_runtime.h>
#include <cstdint>

#define N_LEVELS 16
#define LOG2_T 19
#define HASH_MASK ((1u << LOG2_T) - 1u)
#define P0 73856093u
#define P1 19349663u
#define P2 83492791u

// floor(16 * 2^(l/3)) through the reference fp32 chain (verified in R1).
__device__ constexpr float c_resf[N_LEVELS] = {
    16.f, 20.f, 25.f, 32.f, 40.f, 50.f, 64.f, 80.f,
    101.f, 128.f, 161.f, 203.f, 256.f, 322.f, 406.f, 512.f
};

// Levels 0..8 are densified: entry (cx,cy,bz) -> (E[h(cx,cy,bz)], E[h(cx,cy,bz+1)])
// dims (R+2) x (R+2) x (R+1); cx,cy in [0,R+1] (corner coords), bz in [0,R].
#define N_DENSE 9
__device__ constexpr int c_Rd[N_DENSE] = {16, 20, 25, 32, 40, 50, 64, 80, 101};
__device__ constexpr int c_OFF[N_DENSE] = {
    0, 5508, 15672, 34626, 72774, 145098, 283002, 566142, 1110786
};
#define DENSE_TOTAL 2192904
__device__ float4 g_dense[DENSE_TOTAL];   // ~35 MB scratch (L2-resident)

// ---------------- pre-pass: build dense z-pair tables ----------------
template<int R, int OFF>
__global__ void __launch_bounds__(256) build_level(const float2* __restrict__ tbl)
{
    constexpr int NE = (R + 2) * (R + 2) * (R + 1);
    int idx = blockIdx.x * blockDim.x + threadIdx.x;
    if (idx >= NE) return;
    int bz = idx % (R + 1);
    int t  = idx / (R + 1);
    int cy = t % (R + 2);
    int cx = t / (R + 2);
    unsigned hx  = (unsigned)cx * P0;
    unsigned hy  = (unsigned)cy * P1;
    unsigned hz0 = (unsigned)bz * P2;
    unsigned h0 = (hx ^ hy ^ hz0) & HASH_MASK;
    unsigned h1 = (hx ^ hy ^ (hz0 + P2)) & HASH_MASK;
    float2 e0 = __ldg(tbl + h0);
    float2 e1 = __ldg(tbl + h1);
    g_dense[OFF + idx] = make_float4(e0.x, e0.y, e1.x, e1.y);
}

// ---------------- main kernel ----------------
__global__ void __launch_bounds__(256) hashenc_kernel(
    const float* __restrict__ x,
    const float* __restrict__ emb,
    float* __restrict__ out,
    int B)
{
    const int lane = threadIdx.x & 31;
    const int warp = threadIdx.x >> 5;
    const int i = blockIdx.x * blockDim.x + threadIdx.x;
    const int warpBase = i - lane;
    if (warpBase >= B) return;              // whole-warp uniform exit
    const bool active = (i < B);
    const int ii = active ? i : (B - 1);

    float px = x[3 * ii + 0];
    float py = x[3 * ii + 1];
    float pz = x[3 * ii + 2];
    px = fminf(fmaxf(px, -1.0f), 1.0f);
    py = fminf(fmaxf(py, -1.0f), 1.0f);
    pz = fminf(fmaxf(pz, -1.0f), 1.0f);

    float o[2 * N_LEVELS];

    #pragma unroll
    for (int l = 0; l < N_LEVELS; l++) {
        const float res = c_resf[l];
        const float gs = __fdiv_rn(2.0f, res);

        // exact fp32 chain (must match reference bit decisions for floor)
        float tx  = __fdiv_rn(__fsub_rn(px, -1.0f), gs);
        float fbx = floorf(tx);
        int   bx  = (int)fbx;
        float vx  = __fadd_rn(__fmul_rn(fbx, gs), -1.0f);
        float wx  = __fdiv_rn(__fsub_rn(px, vx), gs);

        float ty  = __fdiv_rn(__fsub_rn(py, -1.0f), gs);
        float fby = floorf(ty);
        int   by  = (int)fby;
        float vy  = __fadd_rn(__fmul_rn(fby, gs), -1.0f);
        float wy  = __fdiv_rn(__fsub_rn(py, vy), gs);

        float tz  = __fdiv_rn(__fsub_rn(pz, -1.0f), gs);
        float fbz = floorf(tz);
        int   bz  = (int)fbz;
        float vz  = __fadd_rn(__fmul_rn(fbz, gs), -1.0f);
        float wz  = __fdiv_rn(__fsub_rn(pz, vz), gs);

        float wx0 = 1.0f - wx;
        float wy0 = 1.0f - wy;
        float wz0 = 1.0f - wz;
        float cxy00 = wx0 * wy0;
        float cxy01 = wx0 * wy;
        float cxy10 = wx  * wy0;
        float cxy11 = wx  * wy;

        float a0, a1;

        if (l < N_DENSE) {
            // dense z-pair path: 4x LDG.128
            const int R  = c_Rd[l];
            const int sy = R + 1;
            const int sx = (R + 2) * (R + 1);
            const float4* dp = g_dense + c_OFF[l];
            int base = bx * sx + by * sy + bz;
            float4 q00 = __ldg(dp + base);
            float4 q01 = __ldg(dp + base + sy);
            float4 q10 = __ldg(dp + base + sx);
            float4 q11 = __ldg(dp + base + sx + sy);

            // z-lerp then xy-weighted sum
            float m00x = fmaf(wz, q00.z, wz0 * q00.x), m00y = fmaf(wz, q00.w, wz0 * q00.y);
            float m01x = fmaf(wz, q01.z, wz0 * q01.x), m01y = fmaf(wz, q01.w, wz0 * q01.y);
            float m10x = fmaf(wz, q10.z, wz0 * q10.x), m10y = fmaf(wz, q10.w, wz0 * q10.y);
            float m11x = fmaf(wz, q11.z, wz0 * q11.x), m11y = fmaf(wz, q11.w, wz0 * q11.y);

            a0 = cxy00 * m00x;            a1 = cxy00 * m00y;
            a0 = fmaf(cxy01, m01x, a0);   a1 = fmaf(cxy01, m01y, a1);
            a0 = fmaf(cxy10, m10x, a0);   a1 = fmaf(cxy10, m10y, a1);
            a0 = fmaf(cxy11, m11x, a0);   a1 = fmaf(cxy11, m11y, a1);
        } else {
            // hashed path: 8x LDG.64
            unsigned hx0 = (unsigned)bx * P0, hx1 = hx0 + P0;
            unsigned hy0 = (unsigned)by * P1, hy1 = hy0 + P1;
            unsigned hz0 = (unsigned)bz * P2, hz1 = hz0 + P2;

            unsigned h0 = (hx0 ^ hy0 ^ hz0) & HASH_MASK;
            unsigned h1 = (hx0 ^ hy0 ^ hz1) & HASH_MASK;
            unsigned h2 = (hx0 ^ hy1 ^ hz0) & HASH_MASK;
            unsigned h3 = (hx0 ^ hy1 ^ hz1) & HASH_MASK;
            unsigned h4 = (hx1 ^ hy0 ^ hz0) & HASH_MASK;
            unsigned h5 = (hx1 ^ hy0 ^ hz1) & HASH_MASK;
            unsigned h6 = (hx1 ^ hy1 ^ hz0) & HASH_MASK;
            unsigned h7 = (hx1 ^ hy1 ^ hz1) & HASH_MASK;

            const float2* tbl = (const float2*)emb + ((size_t)l << LOG2_T);
            float2 e0 = __ldg(tbl + h0);
            float2 e1 = __ldg(tbl + h1);
            float2 e2 = __ldg(tbl + h2);
            float2 e3 = __ldg(tbl + h3);
            float2 e4 = __ldg(tbl + h4);
            float2 e5 = __ldg(tbl + h5);
            float2 e6 = __ldg(tbl + h6);
            float2 e7 = __ldg(tbl + h7);

            float c0 = cxy00 * wz0, c1 = cxy00 * wz;
            float c2 = cxy01 * wz0, c3 = cxy01 * wz;
            float c4 = cxy10 * wz0, c5 = cxy10 * wz;
            float c6 = cxy11 * wz0, c7 = cxy11 * wz;

            a0 = c0 * e0.x;            a1 = c0 * e0.y;
            a0 = fmaf(c1, e1.x, a0);   a1 = fmaf(c1, e1.y, a1);
            a0 = fmaf(c2, e2.x, a0);   a1 = fmaf(c2, e2.y, a1);
            a0 = fmaf(c3, e3.x, a0);   a1 = fmaf(c3, e3.y, a1);
            a0 = fmaf(c4, e4.x, a0);   a1 = fmaf(c4, e4.y, a1);
            a0 = fmaf(c5, e5.x, a0);   a1 = fmaf(c5, e5.y, a1);
            a0 = fmaf(c6, e6.x, a0);   a1 = fmaf(c6, e6.y, a1);
            a0 = fmaf(c7, e7.x, a0);   a1 = fmaf(c7, e7.y, a1);
        }

        o[2 * l + 0] = a0;
        o[2 * l + 1] = a1;
    }

    // ---- coalesced output via warp-level smem transpose ----
    // Each warp owns 32 rows x 128B = 4KB of output. Stage in smem, then
    // 8 fully-coalesced STG.128 (4 lines each) instead of 8x32 scattered lines.
    __shared__ float4 sbuf[8 * 32 * 9];          // stride 9 float4s to dodge bank conflicts
    float4* wb = sbuf + warp * (32 * 9);

    if (warpBase + 32 <= B) {
        #pragma unroll
        for (int s = 0; s < 8; s++)
            wb[lane * 9 + s] = make_float4(o[4*s+0], o[4*s+1], o[4*s+2], o[4*s+3]);
        __syncwarp();
        float4* ob = (float4*)out + (size_t)warpBase * 8;
        #pragma unroll
        for (int k = 0; k < 8; k++) {
            int r = k * 4 + (lane >> 3);
            int s = lane & 7;
            ob[k * 32 + lane] = wb[r * 9 + s];
        }
    } else if (active) {
        float4* po = (float4*)(out + (size_t)i * (2 * N_LEVELS));
        #pragma unroll
        for (int s = 0; s < 8; s++)
            po[s] = make_float4(o[4*s+0], o[4*s+1], o[4*s+2], o[4*s+3]);
    }
}

// ---------------- launch ----------------
template<int R, int OFF>
static inline void launch_build(const float* emb, int level) {
    constexpr int NE = (R + 2) * (R + 2) * (R + 1);
    const float2* tbl = (const float2*)emb + ((size_t)level << LOG2_T);
    build_level<R, OFF><<<(NE + 255) / 256, 256>>>(tbl);
}

extern "C" void kernel_launch(void* const* d_in, const int* in_sizes, int n_in,
                              void* d_out, int out_size) {
    const float* x   = (const float*)d_in[0];
    const float* emb = (const float*)d_in[1];
    float* out = (float*)d_out;
    const int B = in_sizes[0] / 3;

    launch_build< 16,       0>(emb, 0);
    launch_build< 20,    5508>(emb, 1);
    launch_build< 25,   15672>(emb, 2);
    launch_build< 32,   34626>(emb, 3);
    launch_build< 40,   72774>(emb, 4);
    launch_build< 50,  145098>(emb, 5);
    launch_build< 64,  283002>(emb, 6);
    launch_build< 80,  566142>(emb, 7);
    launch_build<101, 1110786>(emb, 8);

    const int threads = 256;
    const int blocks = (B + threads - 1) / threads;
    hashenc_kernel<<<blocks, threads>>>(x, emb, out, B);
}

// round 3
// speedup vs baseline: 1.5065x; 1.2631x over previous
#include <cuda_runtime.h>
#include <cuda_fp16.h>
#include <cstdint>

#define N_LEVELS 16
#define LOG2_T 19
#define HASH_MASK ((1u << LOG2_T) - 1u)
#define P0 73856093u
#define P1 19349663u
#define P2 83492791u

// floor(16 * 2^(l/3)) through the reference fp32 chain (verified in R1).
__device__ constexpr float c_resf[N_LEVELS] = {
    16.f, 20.f, 25.f, 32.f, 40.f, 50.f, 64.f, 80.f,
    101.f, 128.f, 161.f, 203.f, 256.f, 322.f, 406.f, 512.f
};

// Dense levels 0..8: fp16 2x2 corner-block tables.
// Entry (cx, by, bz), cx in [0,R+1], by,bz in [0,R]:
//   uint4 = { h2(y0z0), h2(y0z1), h2(y1z0), h2(y1z1) }  (each half2 = 2 feats)
#define N_DENSE 9
__device__ constexpr int c_Rd[N_DENSE]  = {16, 20, 25, 32, 40, 50, 64, 80, 101};
__device__ constexpr int c_sy[N_DENSE]  = {17, 21, 26, 33, 41, 51, 65, 81, 102};
__device__ constexpr int c_sx[N_DENSE]  = {289, 441, 676, 1089, 1681, 2601, 4225, 6561, 10404};
__device__ constexpr int c_OFF[N_DENSE] = {
    0, 5202, 14904, 33156, 70182, 140784, 276036, 554886, 1092888
};
#define DENSE_TOTAL 2164500
__device__ uint4 g_dense[DENSE_TOTAL];   // ~34.6 MB, L2-resident

__device__ __forceinline__ unsigned pack_h2(float a, float b) {
    __half2 h = __floats2half2_rn(a, b);
    return *reinterpret_cast<unsigned*>(&h);
}

// ---------------- fused pre-pass: build all 9 dense tables ----------------
__global__ void __launch_bounds__(256) build_all(const float* __restrict__ emb)
{
    int idx = blockIdx.x * blockDim.x + threadIdx.x;
    if (idx >= DENSE_TOTAL) return;

    // locate level
    int l = 0;
    #pragma unroll
    for (int k = 1; k < N_DENSE; k++)
        if (idx >= c_OFF[k]) l = k;
    int loc = idx - c_OFF[l];
    int sy = c_sy[l], sx = c_sx[l];

    int cx = loc / sx;
    int r  = loc - cx * sx;
    int by = r / sy;
    int bz = r - by * sy;

    const float2* tbl = (const float2*)emb + ((size_t)l << LOG2_T);
    unsigned hx  = (unsigned)cx * P0;
    unsigned hy0 = (unsigned)by * P1, hy1 = hy0 + P1;
    unsigned hz0 = (unsigned)bz * P2, hz1 = hz0 + P2;

    float2 e00 = __ldg(tbl + ((hx ^ hy0 ^ hz0) & HASH_MASK));
    float2 e01 = __ldg(tbl + ((hx ^ hy0 ^ hz1) & HASH_MASK));
    float2 e10 = __ldg(tbl + ((hx ^ hy1 ^ hz0) & HASH_MASK));
    float2 e11 = __ldg(tbl + ((hx ^ hy1 ^ hz1) & HASH_MASK));

    uint4 q;
    q.x = pack_h2(e00.x, e00.y);
    q.y = pack_h2(e01.x, e01.y);
    q.z = pack_h2(e10.x, e10.y);
    q.w = pack_h2(e11.x, e11.y);
    g_dense[idx] = q;
}

// ---------------- main kernel ----------------
__global__ void __launch_bounds__(256) hashenc_kernel(
    const float* __restrict__ x,
    const float* __restrict__ emb,
    float* __restrict__ out,
    int B)
{
    const int lane = threadIdx.x & 31;
    const int warp = threadIdx.x >> 5;
    const int i = blockIdx.x * blockDim.x + threadIdx.x;
    const int warpBase = i - lane;
    if (warpBase >= B) return;
    const bool active = (i < B);
    const int ii = active ? i : (B - 1);

    float px = x[3 * ii + 0];
    float py = x[3 * ii + 1];
    float pz = x[3 * ii + 2];
    px = fminf(fmaxf(px, -1.0f), 1.0f);
    py = fminf(fmaxf(py, -1.0f), 1.0f);
    pz = fminf(fmaxf(pz, -1.0f), 1.0f);

    float o[2 * N_LEVELS];

    #pragma unroll
    for (int l = 0; l < N_LEVELS; l++) {
        const float res = c_resf[l];
        const float gs = __fdiv_rn(2.0f, res);

        // exact fp32 chain (must match reference bit decisions for floor)
        float tx  = __fdiv_rn(__fsub_rn(px, -1.0f), gs);
        float fbx = floorf(tx);
        int   bx  = (int)fbx;
        float vx  = __fadd_rn(__fmul_rn(fbx, gs), -1.0f);
        float wx  = __fdiv_rn(__fsub_rn(px, vx), gs);

        float ty  = __fdiv_rn(__fsub_rn(py, -1.0f), gs);
        float fby = floorf(ty);
        int   by  = (int)fby;
        float vy  = __fadd_rn(__fmul_rn(fby, gs), -1.0f);
        float wy  = __fdiv_rn(__fsub_rn(py, vy), gs);

        float tz  = __fdiv_rn(__fsub_rn(pz, -1.0f), gs);
        float fbz = floorf(tz);
        int   bz  = (int)fbz;
        float vz  = __fadd_rn(__fmul_rn(fbz, gs), -1.0f);
        float wz  = __fdiv_rn(__fsub_rn(pz, vz), gs);

        float wx0 = 1.0f - wx;
        float wy0 = 1.0f - wy;
        float wz0 = 1.0f - wz;

        float a0, a1;

        if (l < N_DENSE) {
            // dense fp16 2x2-block path: 2x LDG.128 per point
            const int sy = c_sy[l];
            const int sx = c_sx[l];
            const uint4* dp = g_dense + c_OFF[l];
            int base = bx * sx + by * sy + bz;
            uint4 q0 = __ldg(dp + base);        // x = bx
            uint4 q1 = __ldg(dp + base + sx);   // x = bx+1

            float wyz00 = wy0 * wz0;
            float wyz01 = wy0 * wz;
            float wyz10 = wy  * wz0;
            float wyz11 = wy  * wz;

            float2 f00 = __half22float2(*reinterpret_cast<__half2*>(&q0.x));
            float2 f01 = __half22float2(*reinterpret_cast<__half2*>(&q0.y));
            float2 f10 = __half22float2(*reinterpret_cast<__half2*>(&q0.z));
            float2 f11 = __half22float2(*reinterpret_cast<__half2*>(&q0.w));
            float v0x = wyz00 * f00.x;           float v0y = wyz00 * f00.y;
            v0x = fmaf(wyz01, f01.x, v0x);       v0y = fmaf(wyz01, f01.y, v0y);
            v0x = fmaf(wyz10, f10.x, v0x);       v0y = fmaf(wyz10, f10.y, v0y);
            v0x = fmaf(wyz11, f11.x, v0x);       v0y = fmaf(wyz11, f11.y, v0y);

            float2 g00 = __half22float2(*reinterpret_cast<__half2*>(&q1.x));
            float2 g01 = __half22float2(*reinterpret_cast<__half2*>(&q1.y));
            float2 g10 = __half22float2(*reinterpret_cast<__half2*>(&q1.z));
            float2 g11 = __half22float2(*reinterpret_cast<__half2*>(&q1.w));
            float v1x = wyz00 * g00.x;           float v1y = wyz00 * g00.y;
            v1x = fmaf(wyz01, g01.x, v1x);       v1y = fmaf(wyz01, g01.y, v1y);
            v1x = fmaf(wyz10, g10.x, v1x);       v1y = fmaf(wyz10, g10.y, v1y);
            v1x = fmaf(wyz11, g11.x, v1x);       v1y = fmaf(wyz11, g11.y, v1y);

            a0 = fmaf(wx, v1x, wx0 * v0x);
            a1 = fmaf(wx, v1y, wx0 * v0y);
        } else {
            // hashed fp32 path: 8x LDG.64
            unsigned hx0 = (unsigned)bx * P0, hx1 = hx0 + P0;
            unsigned hy0 = (unsigned)by * P1, hy1 = hy0 + P1;
            unsigned hz0 = (unsigned)bz * P2, hz1 = hz0 + P2;

            unsigned h0 = (hx0 ^ hy0 ^ hz0) & HASH_MASK;
            unsigned h1 = (hx0 ^ hy0 ^ hz1) & HASH_MASK;
            unsigned h2 = (hx0 ^ hy1 ^ hz0) & HASH_MASK;
            unsigned h3 = (hx0 ^ hy1 ^ hz1) & HASH_MASK;
            unsigned h4 = (hx1 ^ hy0 ^ hz0) & HASH_MASK;
            unsigned h5 = (hx1 ^ hy0 ^ hz1) & HASH_MASK;
            unsigned h6 = (hx1 ^ hy1 ^ hz0) & HASH_MASK;
            unsigned h7 = (hx1 ^ hy1 ^ hz1) & HASH_MASK;

            const float2* tbl = (const float2*)emb + ((size_t)l << LOG2_T);
            float2 e0 = __ldg(tbl + h0);
            float2 e1 = __ldg(tbl + h1);
            float2 e2 = __ldg(tbl + h2);
            float2 e3 = __ldg(tbl + h3);
            float2 e4 = __ldg(tbl + h4);
            float2 e5 = __ldg(tbl + h5);
            float2 e6 = __ldg(tbl + h6);
            float2 e7 = __ldg(tbl + h7);

            float cxy00 = wx0 * wy0;
            float cxy01 = wx0 * wy;
            float cxy10 = wx  * wy0;
            float cxy11 = wx  * wy;

            float c0 = cxy00 * wz0, c1 = cxy00 * wz;
            float c2 = cxy01 * wz0, c3 = cxy01 * wz;
            float c4 = cxy10 * wz0, c5 = cxy10 * wz;
            float c6 = cxy11 * wz0, c7 = cxy11 * wz;

            a0 = c0 * e0.x;            a1 = c0 * e0.y;
            a0 = fmaf(c1, e1.x, a0);   a1 = fmaf(c1, e1.y, a1);
            a0 = fmaf(c2, e2.x, a0);   a1 = fmaf(c2, e2.y, a1);
            a0 = fmaf(c3, e3.x, a0);   a1 = fmaf(c3, e3.y, a1);
            a0 = fmaf(c4, e4.x, a0);   a1 = fmaf(c4, e4.y, a1);
            a0 = fmaf(c5, e5.x, a0);   a1 = fmaf(c5, e5.y, a1);
            a0 = fmaf(c6, e6.x, a0);   a1 = fmaf(c6, e6.y, a1);
            a0 = fmaf(c7, e7.x, a0);   a1 = fmaf(c7, e7.y, a1);
        }

        o[2 * l + 0] = a0;
        o[2 * l + 1] = a1;
    }

    // ---- coalesced output via warp-level smem transpose ----
    __shared__ float4 sbuf[8 * 32 * 9];
    float4* wb = sbuf + warp * (32 * 9);

    if (warpBase + 32 <= B) {
        #pragma unroll
        for (int s = 0; s < 8; s++)
            wb[lane * 9 + s] = make_float4(o[4*s+0], o[4*s+1], o[4*s+2], o[4*s+3]);
        __syncwarp();
        float4* ob = (float4*)out + (size_t)warpBase * 8;
        #pragma unroll
        for (int k = 0; k < 8; k++) {
            int r = k * 4 + (lane >> 3);
            int s = lane & 7;
            ob[k * 32 + lane] = wb[r * 9 + s];
        }
    } else if (active) {
        float4* po = (float4*)(out + (size_t)i * (2 * N_LEVELS));
        #pragma unroll
        for (int s = 0; s < 8; s++)
            po[s] = make_float4(o[4*s+0], o[4*s+1], o[4*s+2], o[4*s+3]);
    }
}

extern "C" void kernel_launch(void* const* d_in, const int* in_sizes, int n_in,
                              void* d_out, int out_size) {
    const float* x   = (const float*)d_in[0];
    const float* emb = (const float*)d_in[1];
    float* out = (float*)d_out;
    const int B = in_sizes[0] / 3;

    build_all<<<(DENSE_TOTAL + 255) / 256, 256>>>(emb);

    const int threads = 256;
    const int blocks = (B + threads - 1) / threads;
    hashenc_kernel<<<blocks, threads>>>(x, emb, out, B);
}